// round 17
// baseline (speedup 1.0000x reference)
#include <cuda_runtime.h>

// GCN link predictor: 2x GCNConv + edge dot decode.
// R16-proven structure (R7 GEMM tiles, pre-split tf32 hi/lo weights,
// two-stream chunk pipeline) + single-phase full-K W tile in 73.7KB
// dynamic smem (attribute set idempotently in kernel_launch).

#define NMAX    50000
#define CAP     96
#define PROBE_N 2048
#define WSTRIDE 72   // 64 cols + 8 pad; (72k+nc) mod 32 bijective over warp lanes
#define GEMM_SMEM (2 * 128 * WSTRIDE * 4)   // 73728 B: Whi[128][72] + Wlo[128][72]

static __device__ __align__(128) int   g_cnt[NMAX];
static __device__ __align__(128) float g_dinv[NMAX];
static __device__ __align__(128) int   g_bucket[(long)NMAX * CAP];
static __device__ __align__(128) float g_hs1[(long)NMAX * 128];  // x@W1 (raw)
static __device__ __align__(128) float g_t1 [(long)NMAX * 128];  // relu layer-1 out
static __device__ __align__(128) float g_hs2[(long)NMAX * 64];   // t1@W2 (raw)
static __device__ __align__(128) float g_z  [(long)NMAX * 64];
static __device__ __align__(128) float g_W1hi[128 * 128];
static __device__ __align__(128) float g_W1lo[128 * 128];
static __device__ __align__(128) float g_W2hi[128 * 64];
static __device__ __align__(128) float g_W2lo[128 * 64];
static __device__ int g_is64_ei;
static __device__ int g_is64_eli;

// Stream/event handles, once at static init (proven-safe subset).
static cudaStream_t g_s2;
static cudaEvent_t  g_evFork, g_evJoin, g_evG1, g_evB;
namespace {
struct HandleInit {
    HandleInit() {
        cudaStreamCreateWithFlags(&g_s2, cudaStreamNonBlocking);
        cudaEventCreateWithFlags(&g_evFork, cudaEventDisableTiming);
        cudaEventCreateWithFlags(&g_evJoin, cudaEventDisableTiming);
        cudaEventCreateWithFlags(&g_evG1,   cudaEventDisableTiming);
        cudaEventCreateWithFlags(&g_evB,    cudaEventDisableTiming);
    }
} g_hinit;
}

// ---------------------------------------------------------------- init+probe
__global__ void k_init(const unsigned* __restrict__ ei, long ewords,
                       const unsigned* __restrict__ eli, long lwords, int n) {
    int i = blockIdx.x * blockDim.x + threadIdx.x;
    if (i < n) g_cnt[i] = 0;
    if (blockIdx.x == 0) {
        if (threadIdx.x == 0) { g_is64_ei = 1; g_is64_eli = 1; }
        __syncthreads();
        for (int t = threadIdx.x; t < PROBE_N; t += blockDim.x) {
            long idx = 2L * t + 1;
            if (idx < ewords && ei[idx]  != 0u) g_is64_ei  = 0;
            if (idx < lwords && eli[idx] != 0u) g_is64_eli = 0;
        }
    }
}

__device__ __forceinline__ int edge_val(const unsigned* w, long i, int is64) {
    return (int)w[is64 ? (2 * i) : i];
}

__device__ __forceinline__ void build_push(int s, int d, int n) {
    if ((unsigned)s >= (unsigned)n || (unsigned)d >= (unsigned)n) return;
    int pos = atomicAdd(&g_cnt[d], 1);
    if (pos < CAP) g_bucket[(long)d * CAP + pos] = s;
}

__global__ void k_build(const unsigned* __restrict__ ei, int E, int n) {
    int t  = blockIdx.x * blockDim.x + threadIdx.x;
    int e0 = 2 * t;
    if (e0 >= E) return;
    const int  is64 = g_is64_ei;
    const bool has1 = (e0 + 1 < E);

    int s0, s1 = 0, d0, d1 = 0;
    if (is64 && !(E & 1)) {
        const uint4* p = (const uint4*)ei;
        uint4 sv = p[t];
        uint4 dv = p[E / 2 + t];
        s0 = (int)sv.x; s1 = (int)sv.z;
        d0 = (int)dv.x; d1 = (int)dv.z;
    } else if (!is64 && !(E & 1)) {
        const uint2* p = (const uint2*)ei;
        uint2 sv = p[t];
        uint2 dv = p[E / 2 + t];
        s0 = (int)sv.x; s1 = (int)sv.y;
        d0 = (int)dv.x; d1 = (int)dv.y;
    } else {
        s0 = edge_val(ei, e0, is64);
        d0 = edge_val(ei, (long)E + e0, is64);
        if (has1) {
            s1 = edge_val(ei, e0 + 1, is64);
            d1 = edge_val(ei, (long)E + e0 + 1, is64);
        }
    }
    build_push(s0, d0, n);
    if (has1) build_push(s1, d1, n);
}

__global__ void k_dinv(int n) {
    int i = blockIdx.x * blockDim.x + threadIdx.x;
    if (i < n) g_dinv[i] = rsqrtf((float)g_cnt[i] + 1.0f);
}

// ---------------------------------------------------------------- helpers
__device__ __forceinline__ void split_tf32(float x, unsigned& hi, unsigned& lo) {
    asm("cvt.rna.tf32.f32 %0, %1;" : "=r"(hi) : "f"(x));
    float r = x - __uint_as_float(hi);
    asm("cvt.rna.tf32.f32 %0, %1;" : "=r"(lo) : "f"(r));
}

__device__ __forceinline__ void mma_tf32(float c[4],
                                         unsigned a0, unsigned a1,
                                         unsigned a2, unsigned a3,
                                         unsigned b0, unsigned b1) {
    asm volatile(
        "mma.sync.aligned.m16n8k8.row.col.f32.tf32.tf32.f32 "
        "{%0,%1,%2,%3}, {%4,%5,%6,%7}, {%8,%9}, {%0,%1,%2,%3};\n"
        : "+f"(c[0]), "+f"(c[1]), "+f"(c[2]), "+f"(c[3])
        : "r"(a0), "r"(a1), "r"(a2), "r"(a3), "r"(b0), "r"(b1));
}

// Pre-split both weight matrices into tf32 hi/lo (run once, before gemm1).
__global__ void k_splitW(const float* __restrict__ W1,
                         const float* __restrict__ W2) {
    int i = blockIdx.x * blockDim.x + threadIdx.x;
    unsigned hi, lo;
    if (i < 128 * 128) {
        split_tf32(W1[i], hi, lo);
        g_W1hi[i] = __uint_as_float(hi);
        g_W1lo[i] = __uint_as_float(lo);
    }
    if (i < 128 * 64) {
        split_tf32(W2[i], hi, lo);
        g_W2hi[i] = __uint_as_float(hi);
        g_W2lo[i] = __uint_as_float(lo);
    }
}

// ---------------------------------------------------------------- tensor GEMM
// C[rows rowbase..rowlim) = A @ W (raw). 128 rows x 64 cols, 8 warps.
// SINGLE K phase: full 128-k W tile (hi/lo, pre-split) staged once into
// 73.7KB dynamic smem via float4 copies; one __syncthreads; 16 mma k-steps.
// Mainloop fragment math byte-identical to R7/R16.
template <int NCOLS>
__global__ void k_gemm_tc(const float* __restrict__ Aext,
                          int rowbase, int rowlim) {
    extern __shared__ float sm[];
    float (*Whi)[WSTRIDE] = (float(*)[WSTRIDE])sm;
    float (*Wlo)[WSTRIDE] = (float(*)[WSTRIDE])(sm + 128 * WSTRIDE);

    const float* __restrict__ A = (NCOLS == 128) ? Aext : (const float*)g_t1;
    float* __restrict__ outp    = (NCOLS == 128) ? (float*)g_hs1 : (float*)g_hs2;
    const float* __restrict__ Whi_src = (NCOLS == 128) ? g_W1hi : g_W2hi;
    const float* __restrict__ Wlo_src = (NCOLS == 128) ? g_W1lo : g_W2lo;

    const int tid  = threadIdx.x;
    const int lane = tid & 31;
    const int wid  = tid >> 5;
    const int gID  = lane >> 2;
    const int tg   = lane & 3;
    const int col0 = blockIdx.y * 64;

    const int m0 = rowbase + blockIdx.x * 128 + wid * 16;
    const int r0 = m0 + gID;
    const int r1 = r0 + 8;
    const bool v0 = r0 < rowlim, v1 = r1 < rowlim;
    const float* A0 = A + (size_t)(v0 ? r0 : 0) * 128;
    const float* A1 = A + (size_t)(v1 ? r1 : 0) * 128;

    // Stage full 128-k x 64-col W tile (hi/lo) with float4 copies.
#pragma unroll
    for (int idx = tid; idx < 128 * 16; idx += 256) {   // float4 units
        int nc4 = idx & 15;
        int k   = idx >> 4;
        long off = (long)k * NCOLS + col0 + nc4 * 4;
        *(float4*)&Whi[k][nc4 * 4] = *(const float4*)&Whi_src[off];
        *(float4*)&Wlo[k][nc4 * 4] = *(const float4*)&Wlo_src[off];
    }

    float acc[8][4];
#pragma unroll
    for (int i = 0; i < 8; i++)
#pragma unroll
        for (int j = 0; j < 4; j++) acc[i][j] = 0.f;

    __syncthreads();

#pragma unroll
    for (int ks = 0; ks < 16; ks++) {
        const int k0 = ks * 8;
        float f0 = A0[k0 + tg];
        float f1 = A1[k0 + tg];
        float f2 = A0[k0 + tg + 4];
        float f3 = A1[k0 + tg + 4];
        unsigned ah0, al0, ah1, al1, ah2, al2, ah3, al3;
        split_tf32(f0, ah0, al0);
        split_tf32(f1, ah1, al1);
        split_tf32(f2, ah2, al2);
        split_tf32(f3, ah3, al3);

#pragma unroll
        for (int nf = 0; nf < 8; nf++) {
            const int nc = nf * 8 + gID;
            unsigned bh0 = __float_as_uint(Whi[k0 + tg][nc]);
            unsigned bh1 = __float_as_uint(Whi[k0 + tg + 4][nc]);
            unsigned bl0 = __float_as_uint(Wlo[k0 + tg][nc]);
            unsigned bl1 = __float_as_uint(Wlo[k0 + tg + 4][nc]);
            mma_tf32(acc[nf], ah0, ah1, ah2, ah3, bh0, bh1);  // hi*hi
            mma_tf32(acc[nf], ah0, ah1, ah2, ah3, bl0, bl1);  // hi*lo
            mma_tf32(acc[nf], al0, al1, al2, al3, bh0, bh1);  // lo*hi
        }
    }

#pragma unroll
    for (int nf = 0; nf < 8; nf++) {
        int c = col0 + nf * 8 + 2 * tg;
        if (v0) *(float2*)&outp[(long)r0 * NCOLS + c] =
            make_float2(acc[nf][0], acc[nf][1]);
        if (v1) *(float2*)&outp[(long)r1 * NCOLS + c] =
            make_float2(acc[nf][2], acc[nf][3]);
    }
}

// ---------------------------------------------------------------- aggregation
// t1[d] = relu(dinv[d] * (sum_s dinv[s]*h[s] + dinv[d]*h[d]) + b1)
__global__ void k_agg1(const float* __restrict__ b1, int dbase, int dcnt) {
    int w    = (blockIdx.x * blockDim.x + threadIdx.x) >> 5;
    int lane = threadIdx.x & 31;
    if (w >= dcnt) return;
    const int d  = dbase + w;
    const int cc = min(g_cnt[d], CAP);
    const float4* hs = (const float4*)g_hs1;
    const long base = (long)d * CAP;

    float4 acc = make_float4(0.f, 0.f, 0.f, 0.f);
    int k0 = 0;
    for (; k0 + 32 <= cc; k0 += 32) {
        int   sl = g_bucket[base + k0 + lane];
        float dl = g_dinv[sl];
#pragma unroll
        for (int i = 0; i < 32; i++) {
            int   s = __shfl_sync(0xffffffffu, sl, i);
            float ws = __shfl_sync(0xffffffffu, dl, i);
            float4 v = hs[(long)s * 32 + lane];
            acc.x += ws * v.x; acc.y += ws * v.y;
            acc.z += ws * v.z; acc.w += ws * v.w;
        }
    }
    if (k0 < cc) {
        int   sl = (k0 + lane < cc) ? g_bucket[base + k0 + lane] : 0;
        float dl = g_dinv[sl];
        int rem = cc - k0;
        for (int i = 0; i < rem; i++) {
            int   s = __shfl_sync(0xffffffffu, sl, i);
            float ws = __shfl_sync(0xffffffffu, dl, i);
            float4 v = hs[(long)s * 32 + lane];
            acc.x += ws * v.x; acc.y += ws * v.y;
            acc.z += ws * v.z; acc.w += ws * v.w;
        }
    }
    float  di   = g_dinv[d];
    float4 self = hs[(long)d * 32 + lane];
    acc.x += di * self.x; acc.y += di * self.y;
    acc.z += di * self.z; acc.w += di * self.w;
    float4 bb = ((const float4*)b1)[lane];
    float4 o;
    o.x = fmaxf(di * acc.x + bb.x, 0.f);
    o.y = fmaxf(di * acc.y + bb.y, 0.f);
    o.z = fmaxf(di * acc.z + bb.z, 0.f);
    o.w = fmaxf(di * acc.w + bb.w, 0.f);
    ((float4*)g_t1)[(long)d * 32 + lane] = o;
}

__global__ void k_agg2(const float* __restrict__ b2, int n) {
    int gt   = blockIdx.x * blockDim.x + threadIdx.x;
    int grp  = gt >> 4;
    int j    = gt & 15;
    int lane = threadIdx.x & 31;
    unsigned gmask = 0xFFFFu << (lane & 16);
    if (grp >= n) return;
    const int d  = grp;
    const int cc = min(g_cnt[d], CAP);
    const float4* hs = (const float4*)g_hs2;
    const long base = (long)d * CAP;

    float4 acc = make_float4(0.f, 0.f, 0.f, 0.f);
    int k0 = 0;
    for (; k0 + 16 <= cc; k0 += 16) {
        int   sl = g_bucket[base + k0 + j];
        float dl = g_dinv[sl];
#pragma unroll
        for (int i = 0; i < 16; i++) {
            int   s = __shfl_sync(gmask, sl, i, 16);
            float ws = __shfl_sync(gmask, dl, i, 16);
            float4 v = hs[(long)s * 16 + j];
            acc.x += ws * v.x; acc.y += ws * v.y;
            acc.z += ws * v.z; acc.w += ws * v.w;
        }
    }
    if (k0 < cc) {
        int   sl = (k0 + j < cc) ? g_bucket[base + k0 + j] : 0;
        float dl = g_dinv[sl];
        int rem = cc - k0;
        for (int i = 0; i < rem; i++) {
            int   s = __shfl_sync(gmask, sl, i, 16);
            float ws = __shfl_sync(gmask, dl, i, 16);
            float4 v = hs[(long)s * 16 + j];
            acc.x += ws * v.x; acc.y += ws * v.y;
            acc.z += ws * v.z; acc.w += ws * v.w;
        }
    }
    float  di   = g_dinv[d];
    float4 self = hs[(long)d * 16 + j];
    acc.x += di * self.x; acc.y += di * self.y;
    acc.z += di * self.z; acc.w += di * self.w;
    float4 bb = ((const float4*)b2)[j];
    float4 o;
    o.x = di * acc.x + bb.x;
    o.y = di * acc.y + bb.y;
    o.z = di * acc.z + bb.z;
    o.w = di * acc.w + bb.w;
    ((float4*)g_z)[(long)d * 16 + j] = o;
}

// ---------------------------------------------------------------- decode
__global__ void k_decode(const unsigned* __restrict__ eli,
                         float* __restrict__ out, int EL, int n) {
    int gt = blockIdx.x * blockDim.x + threadIdx.x;
    int e  = gt >> 4;
    int j  = gt & 15;
    bool valid = (e < EL);
    int ec = valid ? e : (EL - 1);
    const int is64 = g_is64_eli;
    int u = edge_val(eli, ec, is64);
    int v = edge_val(eli, (long)EL + ec, is64);
    if ((unsigned)u >= (unsigned)n) u = 0;
    if ((unsigned)v >= (unsigned)n) v = 0;
    const float4* z4 = (const float4*)g_z;
    float4 a = z4[(long)u * 16 + j];
    float4 b = z4[(long)v * 16 + j];
    float p = a.x * b.x + a.y * b.y + a.z * b.z + a.w * b.w;
    p += __shfl_xor_sync(0xffffffffu, p, 8, 16);
    p += __shfl_xor_sync(0xffffffffu, p, 4, 16);
    p += __shfl_xor_sync(0xffffffffu, p, 2, 16);
    p += __shfl_xor_sync(0xffffffffu, p, 1, 16);
    if (valid && j == 0) out[e] = p;
}

// ---------------------------------------------------------------- launch
extern "C" void kernel_launch(void* const* d_in, const int* in_sizes, int n_in,
                              void* d_out, int out_size) {
    const float*    x   = (const float*)d_in[0];
    const unsigned* ei  = (const unsigned*)d_in[1];
    const unsigned* eli = (const unsigned*)d_in[2];
    const float*    W1  = (const float*)d_in[3];
    const float*    b1  = (const float*)d_in[4];
    const float*    W2  = (const float*)d_in[5];
    const float*    b2  = (const float*)d_in[6];
    float* out = (float*)d_out;

    const int n  = in_sizes[0] / 128;
    const int E  = in_sizes[1] / 2;
    const int EL = in_sizes[2] / 2;

    // Opt in to 73.7KB dynamic smem (idempotent; runtime is initialized here,
    // unlike the R6 static-ctor attempt; non-stream API, capture-legal).
    cudaFuncSetAttribute(k_gemm_tc<128>,
        cudaFuncAttributeMaxDynamicSharedMemorySize, GEMM_SMEM);
    cudaFuncSetAttribute(k_gemm_tc<64>,
        cudaFuncAttributeMaxDynamicSharedMemorySize, GEMM_SMEM);

    // Node chunks: A = [0, nA) multiple of 128, B = [nA, n).
    const int nA = ((n / 2) / 128) * 128;
    const int nB = n - nA;

    // Fork: side stream builds graph structure during splitW + gemm1.
    cudaEventRecord(g_evFork, 0);
    cudaStreamWaitEvent(g_s2, g_evFork, 0);

    k_init<<<(n + 255) / 256, 256, 0, g_s2>>>(ei, (long)in_sizes[1],
                                              eli, (long)in_sizes[2], n);
    k_build<<<(E / 2 + 255) / 256, 256, 0, g_s2>>>(ei, E, n);
    k_dinv<<<(n + 255) / 256, 256, 0, g_s2>>>(n);
    cudaEventRecord(g_evJoin, g_s2);

    // Main: pre-split weights, then gemm1.
    k_splitW<<<(128 * 128 + 255) / 256, 256>>>(W1, W2);
    dim3 g1((n + 127) / 128, 2);
    k_gemm_tc<128><<<g1, 256, GEMM_SMEM>>>(x, 0, n);
    cudaEventRecord(g_evG1, 0);

    // Main stream: needs graph (evJoin) before aggregation.
    cudaStreamWaitEvent(0, g_evJoin, 0);
    // Side stream: needs gemm1 (evG1) before its agg1 chunk.
    cudaStreamWaitEvent(g_s2, g_evG1, 0);

    // Pipelined chunks: agg1_A/gemm2_A on stream0 || agg1_B/gemm2_B on s2.
    k_agg1<<<(nA * 32 + 255) / 256, 256>>>(b1, 0, nA);
    k_agg1<<<(nB * 32 + 255) / 256, 256, 0, g_s2>>>(b1, nA, nB);

    dim3 g2a(nA / 128, 1);
    k_gemm_tc<64><<<g2a, 256, GEMM_SMEM>>>(nullptr, 0, nA);
    dim3 g2b((nB + 127) / 128, 1);
    k_gemm_tc<64><<<g2b, 256, GEMM_SMEM, g_s2>>>(nullptr, nA, n);
    cudaEventRecord(g_evB, g_s2);
    cudaStreamWaitEvent(0, g_evB, 0);

    k_agg2<<<(n * 16 + 255) / 256, 256>>>(b2, n);

    k_decode<<<((long)EL * 16 + 255) / 256, 256>>>(eli, out, EL, n);
}